// round 12
// baseline (speedup 1.0000x reference)
#include <cuda_runtime.h>
#include <cuda_bf16.h>

// TransientCombNoise: B=32, T=2000, BLOCK=64, MAX_DELAY=480, SR=16000.
// Per row r of N=64000, params (p0..p3):
//   att   = max(16000*(0.0005 + p0*0.0495), 1)   (>= 8)
//   energy= p1 ; tilt = 2*p2 - 1
//   delay = int(64*(0.5 + 0.5*(0.05 + 0.95*p3)))  in [33, 63]
//   y[i]  = env(i)*energy*( n[i] + tilt*exp(delay/att)*n[i-delay] )
//   out   = y * rsqrt(mean(y^2) + 1e-5)
//
// ILP-4: each thread handles the same 4-element slot of FOUR independent rows
// (r, r+16000, r+32000, r+48000). 8 front-batched LDG.128 (MLP=8) hide DRAM/L2
// latency; 16 lanes per row; 4 interleaved shfl.bfly reductions.

#define N_ROWS 64000
#define QTR    (N_ROWS / 4)
#define LOG2E  1.4426950408889634f

__global__ __launch_bounds__(256) void tcn_kernel(
    const float4* __restrict__ params,  // [N_ROWS] float4
    const float*  __restrict__ noise,   // [N_ROWS, 64]
    float*        __restrict__ out)     // [N_ROWS, 64]
{
    const int tid  = blockIdx.x * 256 + threadIdx.x;
    const int slot = tid >> 4;          // row-quad id in [0, QTR)
    const int l    = tid & 15;
    const int i0   = l << 2;

    // ---- front-batched loads: 4 param + 4 noise LDG.128 (MLP = 8) ----
    int    base[4];
    float4 p[4], n[4];
    #pragma unroll
    for (int q = 0; q < 4; ++q) {
        const int row = slot + q * QTR;
        base[q] = row * 64 + i0;        // < 4.1M, fits int
        p[q] = __ldg(params + row);
        n[q] = *reinterpret_cast<const float4*>(noise + base[q]);
    }

    float y[4][4];
    float ss[4];

    #pragma unroll
    for (int q = 0; q < 4; ++q) {
        // Strict-rounded chain so truncated delay matches JAX fp32 exactly.
        const float att    = fmaxf(__fmul_rn(16000.0f,
                             __fadd_rn(0.0005f, __fmul_rn(p[q].x, 0.0495f))), 1.0f);
        const float energy = p[q].y;
        const float tilt   = __fmaf_rn(p[q].z, 2.0f, -1.0f);
        const float bw     = __fadd_rn(0.05f, __fmul_rn(p[q].w, 0.95f));
        int d = (int)__fmul_rn(64.0f, __fadd_rn(0.5f, __fmul_rn(0.5f, bw)));
        d = min(max(d, 1), 480);        // effectively [33, 63]

        float inv_att;
        asm("rcp.approx.f32 %0, %1;" : "=f"(inv_att) : "f"(att));
        const float a2 = -LOG2E * inv_att;      // env(i) = ex2(i*a2)

        float r, e0, etap;
        asm("ex2.approx.f32 %0, %1;" : "=f"(r)    : "f"(a2));
        asm("ex2.approx.f32 %0, %1;" : "=f"(e0)   : "f"((float)i0 * a2));
        asm("ex2.approx.f32 %0, %1;" : "=f"(etap) : "f"(-(float)d * a2));
        e0 *= energy;
        const float e1 = e0 * r, e2 = e1 * r, e3 = e2 * r;
        const float tf = tilt * etap;           // <= |tilt|*e^7.9, no overflow

        // Tap reloads: elements i0+k-d in [0,30] when valid -> L1/L2 hits.
        const int    j  = i0 - d;
        const float* np = noise + (base[q] - d);
        const float m0 = (j + 0 >= 0) ? np[0] : 0.0f;
        const float m1 = (j + 1 >= 0) ? np[1] : 0.0f;
        const float m2 = (j + 2 >= 0) ? np[2] : 0.0f;
        const float m3 = (j + 3 >= 0) ? np[3] : 0.0f;

        y[q][0] = e0 * __fmaf_rn(tf, m0, n[q].x);
        y[q][1] = e1 * __fmaf_rn(tf, m1, n[q].y);
        y[q][2] = e2 * __fmaf_rn(tf, m2, n[q].z);
        y[q][3] = e3 * __fmaf_rn(tf, m3, n[q].w);

        ss[q] = y[q][0] * y[q][0] + y[q][1] * y[q][1]
              + y[q][2] * y[q][2] + y[q][3] * y[q][3];
    }

    // ---- 4 interleaved 16-lane butterfly reductions ----
    #pragma unroll
    for (int o = 8; o > 0; o >>= 1) {
        #pragma unroll
        for (int q = 0; q < 4; ++q)
            ss[q] += __shfl_xor_sync(0xFFFFFFFFu, ss[q], o);
    }

    #pragma unroll
    for (int q = 0; q < 4; ++q) {
        const float ir = rsqrtf(ss[q] * (1.0f / 64.0f) + 1e-5f);
        float4 o;
        o.x = y[q][0] * ir;
        o.y = y[q][1] * ir;
        o.z = y[q][2] * ir;
        o.w = y[q][3] * ir;
        *reinterpret_cast<float4*>(out + base[q]) = o;
    }
}

extern "C" void kernel_launch(void* const* d_in, const int* in_sizes, int n_in,
                              void* d_out, int out_size)
{
    const float4* params = (const float4*)d_in[0];  // [32,2000,4]
    const float*  noise  = (const float*)d_in[1];   // [32,2000,64]
    float* out = (float*)d_out;                     // [32, 2000*64]

    // 16000 row-quads * 16 lanes / 256 threads = 1000 blocks (exact).
    tcn_kernel<<<(QTR * 16) / 256, 256>>>(params, noise, out);
}

// round 14
// speedup vs baseline: 1.2362x; 1.2362x over previous
#include <cuda_runtime.h>
#include <cuda_bf16.h>

// TransientCombNoise: B=32, T=2000, BLOCK=64, MAX_DELAY=480, SR=16000.
// Per row r of N=64000, params (p0..p3):
//   att   = max(16000*(0.0005 + p0*0.0495), 1)   (>= 8)
//   energy= p1 ; tilt = 2*p2 - 1
//   delay = int(64*(0.5 + 0.5*(0.05 + 0.95*p3)))  in [33, 63]
//   y[i]  = env(i)*energy*( n[i] + tilt*exp(delay/att)*n[i-delay] )
//   out   = y * rsqrt(mean(y^2) + 1e-5)
//
// Split-chunk layout: 8 lanes per row, each lane owns elements [4l,4l+3] (lo)
// and [4l+32,4l+35] (hi). Since delay >= 33, the lo chunk NEVER taps (no
// predicates, no tap loads) and only the hi chunk runs the tap machinery
// (4 predicated LDG.32, L1 hits into the row's own 256B). Param math is
// amortized over 8 lanes; RMS is a 3-step butterfly; natural ILP-2 from the
// two chunks. 4 rows per warp, 16000 warps total.

#define N_ROWS 64000
#define LOG2E  1.4426950408889634f

__global__ __launch_bounds__(256) void tcn_kernel(
    const float4* __restrict__ params,  // [N_ROWS] float4
    const float*  __restrict__ noise,   // [N_ROWS, 64]
    float*        __restrict__ out)     // [N_ROWS, 64]
{
    const int tid = blockIdx.x * 256 + threadIdx.x;
    const int row = tid >> 3;           // 8 lanes per row
    const int l   = tid & 7;
    const int i0  = l << 2;             // lo chunk start: 0..28

    const int base = row * 64 + i0;     // < 4.1M, fits int

    // Front-batched loads (MLP = 3): both chunks + params.
    const float4 nlo = *reinterpret_cast<const float4*>(noise + base);
    const float4 nhi = *reinterpret_cast<const float4*>(noise + base + 32);
    const float4 p   = __ldg(params + row);

    // Strict-rounded chain so the truncated delay matches JAX fp32 exactly.
    const float att    = fmaxf(__fmul_rn(16000.0f,
                         __fadd_rn(0.0005f, __fmul_rn(p.x, 0.0495f))), 1.0f);
    const float energy = p.y;
    const float tilt   = __fmaf_rn(p.z, 2.0f, -1.0f);
    const float bw     = __fadd_rn(0.05f, __fmul_rn(p.w, 0.95f));
    int d = (int)__fmul_rn(64.0f, __fadd_rn(0.5f, __fmul_rn(0.5f, bw)));
    d = min(max(d, 1), 480);            // effectively [33, 63]

    float inv_att;
    asm("rcp.approx.f32 %0, %1;" : "=f"(inv_att) : "f"(att));
    const float a2 = -LOG2E * inv_att;  // env(i) = ex2(i*a2)

    float r, e0, e32, etap;
    asm("ex2.approx.f32 %0, %1;" : "=f"(r)    : "f"(a2));
    asm("ex2.approx.f32 %0, %1;" : "=f"(e0)   : "f"((float)i0 * a2));
    asm("ex2.approx.f32 %0, %1;" : "=f"(e32)  : "f"(32.0f * a2));
    asm("ex2.approx.f32 %0, %1;" : "=f"(etap) : "f"(-(float)d * a2));
    e0 *= energy;
    const float e1 = e0 * r, e2 = e1 * r, e3 = e2 * r;
    const float tf = tilt * etap;       // <= |tilt|*e^7.9, no overflow

    // lo chunk: elements i0..i0+3 <= 31 < 33 <= d  =>  never tapped.
    const float y0 = e0 * nlo.x;
    const float y1 = e1 * nlo.y;
    const float y2 = e2 * nlo.z;
    const float y3 = e3 * nlo.w;

    // hi chunk: element i = i0+32+k, tap j = i-d in [-31, 30].
    const int    jb = i0 + 32 - d;      // may be negative
    const float* np = noise + (row * 64 + jb);   // L1 hits (row's own 256B)
    const float m0 = (jb + 0 >= 0) ? np[0] : 0.0f;
    const float m1 = (jb + 1 >= 0) ? np[1] : 0.0f;
    const float m2 = (jb + 2 >= 0) ? np[2] : 0.0f;
    const float m3 = (jb + 3 >= 0) ? np[3] : 0.0f;

    const float f0 = e0 * e32, f1 = e1 * e32, f2 = e2 * e32, f3 = e3 * e32;
    const float z0 = f0 * __fmaf_rn(tf, m0, nhi.x);
    const float z1 = f1 * __fmaf_rn(tf, m1, nhi.y);
    const float z2 = f2 * __fmaf_rn(tf, m2, nhi.z);
    const float z3 = f3 * __fmaf_rn(tf, m3, nhi.w);

    // Sum of squares across the 8-lane row group (3-step butterfly).
    float ss = (y0 * y0 + y1 * y1 + y2 * y2 + y3 * y3)
             + (z0 * z0 + z1 * z1 + z2 * z2 + z3 * z3);
    ss += __shfl_xor_sync(0xFFFFFFFFu, ss, 4);
    ss += __shfl_xor_sync(0xFFFFFFFFu, ss, 2);
    ss += __shfl_xor_sync(0xFFFFFFFFu, ss, 1);

    const float ir = rsqrtf(ss * (1.0f / 64.0f) + 1e-5f);

    float4 olo, ohi;
    olo.x = y0 * ir;  olo.y = y1 * ir;  olo.z = y2 * ir;  olo.w = y3 * ir;
    ohi.x = z0 * ir;  ohi.y = z1 * ir;  ohi.z = z2 * ir;  ohi.w = z3 * ir;
    *reinterpret_cast<float4*>(out + base)      = olo;
    *reinterpret_cast<float4*>(out + base + 32) = ohi;
}

extern "C" void kernel_launch(void* const* d_in, const int* in_sizes, int n_in,
                              void* d_out, int out_size)
{
    const float4* params = (const float4*)d_in[0];  // [32,2000,4]
    const float*  noise  = (const float*)d_in[1];   // [32,2000,64]
    float* out = (float*)d_out;                     // [32, 2000*64]

    // 64000 rows * 8 lanes / 256 threads = 2000 blocks (exact).
    tcn_kernel<<<(N_ROWS * 8) / 256, 256>>>(params, noise, out);
}